// round 3
// baseline (speedup 1.0000x reference)
#include <cuda_runtime.h>
#include <cstdint>

#define BB    16
#define CC    512
#define NPOS  400
#define HID   256
#define NEMB  30
#define TT    201
#define OUTW  38
#define XP    544       // padded wih row (512 ctx + 30 emb(+bih) + 2 pad)
#define RCL   8
#define NLOC  50
#define NTHR  1024
#define FSTR  516       // padded feat row stride

// ---------------- device scratch ----------------
__device__ float g_i2h4[CC * HID];       // [c/4][h][4] interleaved for LDG.128
__device__ float g_Wcomb[OUTW * HID];    // fused output heads
__device__ float g_bcomb[OUTW];
__device__ float g_h2hT[HID * HID];      // h2h transposed: [j][i]
__device__ float g_wihP[3 * HID * XP];   // padded wih, bih folded into cols 512..541

// ---------------- helpers ----------------
__device__ __forceinline__ uint32_t smem_u32(const void* p) {
    return (uint32_t)__cvta_generic_to_shared(p);
}
__device__ __forceinline__ uint32_t mapa_u32(uint32_t addr, uint32_t rank) {
    uint32_t r;
    asm("mapa.shared::cluster.u32 %0, %1, %2;" : "=r"(r) : "r"(addr), "r"(rank));
    return r;
}
__device__ __forceinline__ float ld_dsm(uint32_t a) {
    float v;
    asm volatile("ld.shared::cluster.f32 %0, [%1];" : "=f"(v) : "r"(a));
    return v;
}
__device__ __forceinline__ void st_dsm(uint32_t a, float v) {
    asm volatile("st.shared::cluster.f32 [%0], %1;" :: "r"(a), "f"(v));
}
#define CLUSTER_SYNC() do { \
    asm volatile("barrier.cluster.arrive.aligned;" ::: "memory"); \
    asm volatile("barrier.cluster.wait.aligned;"   ::: "memory"); } while (0)
#define BAR1_768() asm volatile("bar.sync 1, 768;" ::: "memory")

__device__ __forceinline__ float sigmoidf_(float x) {
    return __fdividef(1.f, 1.f + __expf(-x));
}
__device__ __forceinline__ float tanh_acc(float x) {   // accurate-ish (GRU)
    float cx = fminf(fmaxf(x, -15.f), 15.f);
    float e = __expf(2.f * cx);
    return __fdividef(e - 1.f, e + 1.f);
}
__device__ __forceinline__ float tanh_fast(float x) {  // HW tanh (attention)
    float y;
    asm("tanh.approx.f32 %0, %1;" : "=f"(y) : "f"(x));
    return y;
}
__device__ __forceinline__ float4 f4(const float* p) { return *(const float4*)p; }

// ---------------- prep kernel ----------------
__global__ void prep_kernel(const float* __restrict__ i2h, const float* __restrict__ h2h_w,
                            const float* __restrict__ wih, const float* __restrict__ bih,
                            const float* __restrict__ sg1w, const float* __restrict__ sg1b,
                            const float* __restrict__ sg2w, const float* __restrict__ sg2b,
                            const float* __restrict__ lg1w, const float* __restrict__ lg1b,
                            const float* __restrict__ lg2w, const float* __restrict__ lg2b) {
    int blk = blockIdx.x, tid = threadIdx.x;
    if (blk < OUTW) {
        const float *W2, *W1, *b1, *b2; int row;
        if (blk < NEMB) { row = blk;        W2 = sg2w; W1 = sg1w; b1 = sg1b; b2 = sg2b; }
        else            { row = blk - NEMB; W2 = lg2w; W1 = lg1w; b1 = lg1b; b2 = lg2b; }
        float acc = 0.f;
        for (int k = 0; k < HID; k++) acc += W2[row * HID + k] * W1[k * HID + tid];
        g_Wcomb[blk * HID + tid] = acc;
        __shared__ float red[HID];
        red[tid] = W2[row * HID + tid] * b1[tid];
        __syncthreads();
        for (int s = HID / 2; s > 0; s >>= 1) {
            if (tid < s) red[tid] += red[tid + s];
            __syncthreads();
        }
        if (tid == 0) g_bcomb[blk] = red[0] + b2[row];
    } else if (blk < OUTW + CC) {
        int c = blk - OUTW;
        g_i2h4[(c >> 2) * HID * 4 + tid * 4 + (c & 3)] = i2h[tid * CC + c];
    } else if (blk < OUTW + CC + HID) {
        int j = blk - OUTW - CC;
        g_h2hT[j * HID + tid] = h2h_w[tid * HID + j];
    } else {
        int m = blk - OUTW - CC - HID;           // 0..767
        for (int c = tid; c < XP; c += HID) {
            float v = 0.f;
            if (c < 512)      v = wih[m * 542 + c];
            else if (c < 542) v = wih[m * 542 + c] + bih[m];
            g_wihP[m * XP + c] = v;
        }
    }
}

// ---------------- shared memory ----------------
struct __align__(16) Smem {
    float feat[NLOC * FSTR];     // local feat slice [nl][c]
    float hproj[NLOC * HID];     // local i2h(feat) slice
    float pp[HID];               // full prev_proj (sum of partials + bias)
    float pp_part[HID];          // my column-partial of prev_proj
    float ctx[CC];               // full unnormalized context
    float part_ctx[CC];          // my partial context
    float red[CC];               // reduce staging (64 ch x 8 peers)
    float h2hb[HID];
    float hid[2][HID];           // double-buffered hidden
    float gh[96];                // whh@h + bhh, [gate*32 + unit]
    float hloc[32];              // local new hidden values
    float wexp[64];
    float es;
    float inv_es;
    float pad[2];
};

// ---------------- main persistent cluster kernel ----------------
__global__ void __launch_bounds__(NTHR, 1) __cluster_dims__(RCL, 1, 1)
sla_kernel(const float* __restrict__ fea, const int* __restrict__ structure,
           const float* __restrict__ h2h_b, const float* __restrict__ score_w,
           const float* __restrict__ whh, const float* __restrict__ bhh,
           float* __restrict__ out) {
    extern __shared__ char smem_raw[];
    Smem* sm = (Smem*)smem_raw;
    const int tid  = threadIdx.x;
    const int lane = tid & 31;
    const int wid  = tid >> 5;
    const int b    = blockIdx.x >> 3;
    const int r    = blockIdx.x & 7;

    // ---- prologue: load feat slice, biases, zero state ----
    {
        const float* fb = fea + (size_t)b * CC * NPOS;
        for (int idx = tid; idx < NLOC * CC; idx += NTHR) {
            int c  = idx / NLOC;
            int nl = idx - c * NLOC;
            sm->feat[nl * FSTR + c] = fb[c * NPOS + r * NLOC + nl];
        }
        for (int i = tid; i < HID; i += NTHR) {
            sm->h2hb[i]    = h2h_b[i];
            sm->hid[0][i]  = 0.f;
            sm->hid[1][i]  = 0.f;
            sm->pp_part[i] = 0.f;
        }
    }
    __syncthreads();

    // ---- prologue: hproj[nl][h] = sum_c feat[nl][c] * i2h[h][c] ----
    {
        int h  = tid & 255;
        int g  = tid >> 8;            // 0..3
        int n0 = g * 13;
        float acc[13];
        #pragma unroll
        for (int i = 0; i < 13; i++) acc[i] = 0.f;
        for (int cb = 0; cb < CC / 4; cb++) {
            float4 w = f4(&g_i2h4[cb * HID * 4 + h * 4]);
            #pragma unroll
            for (int i = 0; i < 13; i++) {
                int n = n0 + i;
                if (n < NLOC) {
                    float4 fv = f4(&sm->feat[n * FSTR + cb * 4]);
                    acc[i] += fv.x * w.x + fv.y * w.y + fv.z * w.z + fv.w * w.w;
                }
            }
        }
        #pragma unroll
        for (int i = 0; i < 13; i++) {
            int n = n0 + i;
            if (n < NLOC) sm->hproj[n * HID + h] = acc[i];
        }
    }

    // persistent score regs for attention warps
    float4 sv0 = make_float4(0.f, 0.f, 0.f, 0.f), sv1 = sv0;
    if (wid < 24) {
        sv0 = f4(&score_w[lane * 8]);
        sv1 = f4(&score_w[lane * 8 + 4]);
    }
    CLUSTER_SYNC();

    // ---- decode loop (t == TT is the output-only epilogue) ----
    for (int t = 0; t <= TT; t++) {
        const int cur = t & 1, nxt = cur ^ 1;

        // ================= PHASE 1 =================
        if (wid >= 24) {
            // hid[cur] regs (full hidden, assembled last step)
            float4 h0 = f4(&sm->hid[cur][lane * 8]);
            float4 h1 = f4(&sm->hid[cur][lane * 8 + 4]);
            if (t < TT) {
                // gh: 12 gate-rows of whh @ hid + bhh
                #pragma unroll 4
                for (int i = 0; i < 12; i++) {
                    int m2 = (wid - 24) * 12 + i;     // 0..95
                    int g  = m2 >> 5, u = m2 & 31;
                    const float* wr = whh + (size_t)(g * HID + r * 32 + u) * HID + lane * 8;
                    float4 w0 = f4(wr), w1 = f4(wr + 4);
                    float a = w0.x * h0.x + w0.y * h0.y + w0.z * h0.z + w0.w * h0.w
                            + w1.x * h1.x + w1.y * h1.y + w1.z * h1.z + w1.w * h1.w;
                    #pragma unroll
                    for (int o = 16; o > 0; o >>= 1) a += __shfl_xor_sync(0xffffffffu, a, o);
                    if (lane == 0) sm->gh[m2] = a + bhh[g * HID + r * 32 + u];
                }
            }
            if (t > 0 && wid < 29) {
                int ow = r + 8 * (wid - 24);
                if (ow < OUTW) {
                    const float* wr = g_Wcomb + ow * HID + lane * 8;
                    float4 w0 = f4(wr), w1 = f4(wr + 4);
                    float a = w0.x * h0.x + w0.y * h0.y + w0.z * h0.z + w0.w * h0.w
                            + w1.x * h1.x + w1.y * h1.y + w1.z * h1.z + w1.w * h1.w;
                    #pragma unroll
                    for (int o = 16; o > 0; o >>= 1) a += __shfl_xor_sync(0xffffffffu, a, o);
                    if (lane == 0) {
                        a += g_bcomb[ow];
                        if (ow >= NEMB) a = sigmoidf_(a);
                        out[((size_t)b * TT + (t - 1)) * OUTW + ow] = a;
                    }
                }
            }
        } else if (t < TT) {
            // assemble full prev_proj: sum of 8 column-partials + bias
            if (tid < HID) {
                uint32_t base = smem_u32(&sm->pp_part[tid]);
                float acc = sm->h2hb[tid];
                #pragma unroll
                for (int p = 0; p < RCL; p++) acc += ld_dsm(mapa_u32(base, p));
                sm->pp[tid] = acc;
            }
            BAR1_768();
            // attention: rows 2*wid, 2*wid+1 (+48+wid for wid<2)
            {
                float4 pv0 = f4(&sm->pp[lane * 8]);
                float4 pv1 = f4(&sm->pp[lane * 8 + 4]);
                int rows[3]; int nr = 2;
                rows[0] = 2 * wid; rows[1] = 2 * wid + 1;
                if (wid < 2) { rows[2] = 48 + wid; nr = 3; }
                for (int q = 0; q < nr; q++) {
                    int n = rows[q];
                    const float* hp = &sm->hproj[n * HID + lane * 8];
                    float4 h0 = f4(hp), h1 = f4(hp + 4);
                    float a = tanh_fast(h0.x + pv0.x) * sv0.x
                            + tanh_fast(h0.y + pv0.y) * sv0.y
                            + tanh_fast(h0.z + pv0.z) * sv0.z
                            + tanh_fast(h0.w + pv0.w) * sv0.w
                            + tanh_fast(h1.x + pv1.x) * sv1.x
                            + tanh_fast(h1.y + pv1.y) * sv1.y
                            + tanh_fast(h1.z + pv1.z) * sv1.z
                            + tanh_fast(h1.w + pv1.w) * sv1.w;
                    #pragma unroll
                    for (int o = 16; o > 0; o >>= 1) a += __shfl_xor_sync(0xffffffffu, a, o);
                    if (lane == 0) sm->wexp[n] = __expf(a);
                }
            }
            BAR1_768();
            if (wid < 4) {           // partial context, 128 threads x float4
                float4 a = make_float4(0.f, 0.f, 0.f, 0.f);
                #pragma unroll 5
                for (int n = 0; n < NLOC; n++) {
                    float w = sm->wexp[n];
                    float4 fv = f4(&sm->feat[n * FSTR + tid * 4]);
                    a.x += w * fv.x; a.y += w * fv.y; a.z += w * fv.z; a.w += w * fv.w;
                }
                *(float4*)&sm->part_ctx[tid * 4] = a;
            }
            if (wid == 16) {         // local expsum
                float v = (lane < 25) ? sm->wexp[lane] + sm->wexp[lane + 25] : 0.f;
                #pragma unroll
                for (int o = 16; o > 0; o >>= 1) v += __shfl_xor_sync(0xffffffffu, v, o);
                if (lane == 0) sm->es = v;
            }
        }
        if (t == TT) break;

        CLUSTER_SYNC();   // S2: part_ctx/es ready everywhere

        // ================= PHASE 2 =================
        // gather my 64-channel chunk from 8 peers
        if (tid < CC) {
            int cl = tid >> 3, p = tid & 7;
            sm->red[tid] = ld_dsm(mapa_u32(smem_u32(&sm->part_ctx[r * 64 + cl]), p));
        }
        if (wid == 16 && lane < 8) {     // expsum all-reduce -> inv_es
            float e = ld_dsm(mapa_u32(smem_u32(&sm->es), lane));
            e += __shfl_xor_sync(0xffu, e, 1);
            e += __shfl_xor_sync(0xffu, e, 2);
            e += __shfl_xor_sync(0xffu, e, 4);
            if (lane == 0) sm->inv_es = __fdividef(1.f, e);
        }
        __syncthreads();
        if (tid < 64) {                  // reduce + scatter chunk to all peers
            float s = 0.f;
            #pragma unroll
            for (int p = 0; p < RCL; p++) s += sm->red[tid * 8 + p];
            uint32_t base = smem_u32(&sm->ctx[r * 64 + tid]);
            #pragma unroll
            for (int p = 0; p < RCL; p++) st_dsm(mapa_u32(base, p), s);
        }
        CLUSTER_SYNC();   // S3: full ctx ready everywhere

        // GRU input GEMV + cell update; warp wid owns unit j = r*32+wid
        {
            const int ch = structure[b * TT + t];
            const int j  = r * 32 + wid;
            float4 c0 = f4(&sm->ctx[0 * 128 + lane * 4]);
            float4 c1 = f4(&sm->ctx[1 * 128 + lane * 4]);
            float4 c2 = f4(&sm->ctx[2 * 128 + lane * 4]);
            float4 c3 = f4(&sm->ctx[3 * 128 + lane * 4]);
            float ag[3];
            #pragma unroll
            for (int g = 0; g < 3; g++) {
                const float* wr = g_wihP + (size_t)(g * HID + j) * XP + lane * 4;
                float4 w0 = f4(wr), w1 = f4(wr + 128), w2 = f4(wr + 256), w3 = f4(wr + 384);
                float a = w0.x * c0.x + w0.y * c0.y + w0.z * c0.z + w0.w * c0.w;
                a += w1.x * c1.x + w1.y * c1.y + w1.z * c1.z + w1.w * c1.w;
                a += w2.x * c2.x + w2.y * c2.y + w2.z * c2.z + w2.w * c2.w;
                a += w3.x * c3.x + w3.y * c3.y + w3.z * c3.z + w3.w * c3.w;
                ag[g] = a;
            }
            #pragma unroll
            for (int o = 16; o > 0; o >>= 1) {
                ag[0] += __shfl_xor_sync(0xffffffffu, ag[0], o);
                ag[1] += __shfl_xor_sync(0xffffffffu, ag[1], o);
                ag[2] += __shfl_xor_sync(0xffffffffu, ag[2], o);
            }
            float hnew = 0.f;
            if (lane == 0) {
                float inv = sm->inv_es;
                float ir = ag[0] * inv + g_wihP[(size_t)(0 * HID + j) * XP + 512 + ch];
                float iz = ag[1] * inv + g_wihP[(size_t)(1 * HID + j) * XP + 512 + ch];
                float in_ = ag[2] * inv + g_wihP[(size_t)(2 * HID + j) * XP + 512 + ch];
                float hr = sm->gh[wid], hz = sm->gh[32 + wid], hn = sm->gh[64 + wid];
                float rg = sigmoidf_(ir + hr);
                float zg = sigmoidf_(iz + hz);
                float ng = tanh_acc(in_ + rg * hn);
                hnew = (1.f - zg) * ng + zg * sm->hid[cur][j];
            }
            hnew = __shfl_sync(0xffffffffu, hnew, 0);
            if (lane < RCL)
                st_dsm(mapa_u32(smem_u32(&sm->hid[nxt][j]), lane), hnew);
            if (lane == 0) sm->hloc[wid] = hnew;
        }
        __syncthreads();
        // column-partial of next prev_proj from local hidden units (needs only hloc)
        if (tid < 64) {
            float4 a = make_float4(0.f, 0.f, 0.f, 0.f);
            #pragma unroll 8
            for (int k = 0; k < 32; k++) {
                float hv = sm->hloc[k];
                float4 w = f4(&g_h2hT[(size_t)(r * 32 + k) * HID + tid * 4]);
                a.x += hv * w.x; a.y += hv * w.y; a.z += hv * w.z; a.w += hv * w.w;
            }
            *(float4*)&sm->pp_part[tid * 4] = a;
        }
        CLUSTER_SYNC();   // S1: pp_part + hid[nxt] ready for next step
    }
}

// ---------------- launch ----------------
extern "C" void kernel_launch(void* const* d_in, const int* in_sizes, int n_in,
                              void* d_out, int out_size) {
    const float* fea       = (const float*)d_in[0];
    const int*   structure = (const int*)  d_in[1];
    const float* i2h_w     = (const float*)d_in[2];
    const float* h2h_w     = (const float*)d_in[3];
    const float* h2h_b     = (const float*)d_in[4];
    const float* score_w   = (const float*)d_in[5];
    const float* gru_wih   = (const float*)d_in[6];
    const float* gru_bih   = (const float*)d_in[7];
    const float* gru_whh   = (const float*)d_in[8];
    const float* gru_bhh   = (const float*)d_in[9];
    const float* sg1_w     = (const float*)d_in[10];
    const float* sg1_b     = (const float*)d_in[11];
    const float* sg2_w     = (const float*)d_in[12];
    const float* sg2_b     = (const float*)d_in[13];
    const float* lg1_w     = (const float*)d_in[14];
    const float* lg1_b     = (const float*)d_in[15];
    const float* lg2_w     = (const float*)d_in[16];
    const float* lg2_b     = (const float*)d_in[17];
    float* out = (float*)d_out;

    prep_kernel<<<OUTW + CC + HID + 3 * HID, HID>>>(
        i2h_w, h2h_w, gru_wih, gru_bih,
        sg1_w, sg1_b, sg2_w, sg2_b, lg1_w, lg1_b, lg2_w, lg2_b);

    cudaFuncSetAttribute(sla_kernel, cudaFuncAttributeMaxDynamicSharedMemorySize,
                         (int)sizeof(Smem));
    sla_kernel<<<BB * RCL, NTHR, sizeof(Smem)>>>(
        fea, structure, h2h_b, score_w, gru_whh, gru_bhh, out);
}

// round 6
// speedup vs baseline: 1.2266x; 1.2266x over previous
#include <cuda_runtime.h>
#include <cstdint>

#define BB    16
#define CC    512
#define NPOS  400
#define HID   256
#define NEMB  30
#define TT    201
#define OUTW  38
#define XP    544       // padded wih row (512 ctx + 30 emb(+bih) + 2 pad)
#define RCL   8
#define NLOC  50
#define NTHR  1024
#define FSTR  516       // padded feat row stride

// ---------------- device scratch ----------------
__device__ float g_i2h4[CC * HID];       // [c/4][h][4] interleaved for LDG.128
__device__ float g_Wcomb[OUTW * HID];    // fused output heads
__device__ float g_bcomb[OUTW];
__device__ float g_h2hT[HID * HID];      // h2h transposed: [j][i]
__device__ float g_wihP[3 * HID * XP];   // padded wih, bih folded into cols 512..541

// ---------------- helpers ----------------
__device__ __forceinline__ uint32_t smem_u32(const void* p) {
    return (uint32_t)__cvta_generic_to_shared(p);
}
__device__ __forceinline__ uint32_t mapa_u32(uint32_t addr, uint32_t rank) {
    uint32_t r;
    asm("mapa.shared::cluster.u32 %0, %1, %2;" : "=r"(r) : "r"(addr), "r"(rank));
    return r;
}
__device__ __forceinline__ float ld_dsm(uint32_t a) {
    float v;
    asm volatile("ld.shared::cluster.f32 %0, [%1];" : "=f"(v) : "r"(a));
    return v;
}
__device__ __forceinline__ void st_dsm(uint32_t a, float v) {
    asm volatile("st.shared::cluster.f32 [%0], %1;" :: "r"(a), "f"(v));
}
#define CLUSTER_SYNC() do { \
    asm volatile("barrier.cluster.arrive.aligned;" ::: "memory"); \
    asm volatile("barrier.cluster.wait.aligned;"   ::: "memory"); } while (0)
#define BAR1_768() asm volatile("bar.sync 1, 768;" ::: "memory")

__device__ __forceinline__ float sigmoidf_(float x) {
    return __fdividef(1.f, 1.f + __expf(-x));
}
__device__ __forceinline__ float tanh_acc(float x) {   // accurate-ish (GRU)
    float cx = fminf(fmaxf(x, -15.f), 15.f);
    float e = __expf(2.f * cx);
    return __fdividef(e - 1.f, e + 1.f);
}
__device__ __forceinline__ float tanh_fast(float x) {  // HW tanh (attention)
    float y;
    asm("tanh.approx.f32 %0, %1;" : "=f"(y) : "f"(x));
    return y;
}
__device__ __forceinline__ float4 f4(const float* p) { return *(const float4*)p; }

// ---------------- prep kernel ----------------
__global__ void prep_kernel(const float* __restrict__ i2h, const float* __restrict__ h2h_w,
                            const float* __restrict__ wih, const float* __restrict__ bih,
                            const float* __restrict__ sg1w, const float* __restrict__ sg1b,
                            const float* __restrict__ sg2w, const float* __restrict__ sg2b,
                            const float* __restrict__ lg1w, const float* __restrict__ lg1b,
                            const float* __restrict__ lg2w, const float* __restrict__ lg2b) {
    int blk = blockIdx.x, tid = threadIdx.x;
    if (blk < OUTW) {
        const float *W2, *W1, *b1, *b2; int row;
        if (blk < NEMB) { row = blk;        W2 = sg2w; W1 = sg1w; b1 = sg1b; b2 = sg2b; }
        else            { row = blk - NEMB; W2 = lg2w; W1 = lg1w; b1 = lg1b; b2 = lg2b; }
        float acc = 0.f;
        for (int k = 0; k < HID; k++) acc += W2[row * HID + k] * W1[k * HID + tid];
        g_Wcomb[blk * HID + tid] = acc;
        __shared__ float red[HID];
        red[tid] = W2[row * HID + tid] * b1[tid];
        __syncthreads();
        for (int s = HID / 2; s > 0; s >>= 1) {
            if (tid < s) red[tid] += red[tid + s];
            __syncthreads();
        }
        if (tid == 0) g_bcomb[blk] = red[0] + b2[row];
    } else if (blk < OUTW + CC) {
        int c = blk - OUTW;
        g_i2h4[(c >> 2) * HID * 4 + tid * 4 + (c & 3)] = i2h[tid * CC + c];
    } else if (blk < OUTW + CC + HID) {
        int j = blk - OUTW - CC;
        g_h2hT[j * HID + tid] = h2h_w[tid * HID + j];
    } else {
        int m = blk - OUTW - CC - HID;           // 0..767
        for (int c = tid; c < XP; c += HID) {
            float v = 0.f;
            if (c < 512)      v = wih[m * 542 + c];
            else if (c < 542) v = wih[m * 542 + c] + bih[m];
            g_wihP[m * XP + c] = v;
        }
    }
}

// ---------------- shared memory ----------------
struct __align__(16) Smem {
    float feat[NLOC * FSTR];     // local feat slice [nl][c]
    float hproj[NLOC * HID];     // local i2h(feat) slice
    float h2hs[32 * HID];        // SMEM-cached h2hT slice: rows r*32..r*32+31
    float pp[HID];               // full prev_proj (sum of partials + bias)
    float pp_part[HID];          // my column-partial of prev_proj
    float part_ctx[516];         // my partial context (+ es at [512]; 516 keeps 16B alignment)
    float ctxS[516];             // all-reduced context (+ expsum at [512])
    float h2hb[HID];
    float hid[2][HID];           // double-buffered hidden
    float gh[96];                // whh@h + bhh, [gate*32 + unit]
    float hloc[32];              // local new hidden values
    float wexp[64];
    float pad[4];
};

// ---------------- main persistent cluster kernel ----------------
__global__ void __launch_bounds__(NTHR, 1) __cluster_dims__(RCL, 1, 1)
sla_kernel(const float* __restrict__ fea, const int* __restrict__ structure,
           const float* __restrict__ h2h_b, const float* __restrict__ score_w,
           const float* __restrict__ whh, const float* __restrict__ bhh,
           float* __restrict__ out) {
    extern __shared__ char smem_raw[];
    Smem* sm = (Smem*)smem_raw;
    const int tid  = threadIdx.x;
    const int lane = tid & 31;
    const int wid  = tid >> 5;
    const int b    = blockIdx.x >> 3;
    const int r    = blockIdx.x & 7;

    // ---- prologue: load feat slice, h2hT slice, biases, zero state ----
    {
        const float* fb = fea + (size_t)b * CC * NPOS;
        for (int idx = tid; idx < NLOC * CC; idx += NTHR) {
            int c  = idx / NLOC;
            int nl = idx - c * NLOC;
            sm->feat[nl * FSTR + c] = fb[c * NPOS + r * NLOC + nl];
        }
        for (int i = tid; i < 32 * HID; i += NTHR)
            sm->h2hs[i] = g_h2hT[(size_t)(r * 32) * HID + i];
        for (int i = tid; i < HID; i += NTHR) {
            sm->h2hb[i]    = h2h_b[i];
            sm->hid[0][i]  = 0.f;
            sm->hid[1][i]  = 0.f;
            sm->pp_part[i] = 0.f;
        }
    }
    __syncthreads();

    // ---- prologue: hproj[nl][h] = sum_c feat[nl][c] * i2h[h][c] ----
    {
        int h  = tid & 255;
        int g  = tid >> 8;            // 0..3
        int n0 = g * 13;
        float acc[13];
        #pragma unroll
        for (int i = 0; i < 13; i++) acc[i] = 0.f;
        for (int cb = 0; cb < CC / 4; cb++) {
            float4 w = f4(&g_i2h4[cb * HID * 4 + h * 4]);
            #pragma unroll
            for (int i = 0; i < 13; i++) {
                int n = n0 + i;
                if (n < NLOC) {
                    float4 fv = f4(&sm->feat[n * FSTR + cb * 4]);
                    acc[i] += fv.x * w.x + fv.y * w.y + fv.z * w.z + fv.w * w.w;
                }
            }
        }
        #pragma unroll
        for (int i = 0; i < 13; i++) {
            int n = n0 + i;
            if (n < NLOC) sm->hproj[n * HID + h] = acc[i];
        }
    }

    // persistent score regs for attention warps
    float4 sv0 = make_float4(0.f, 0.f, 0.f, 0.f), sv1 = sv0;
    if (wid < 24) {
        sv0 = f4(&score_w[lane * 8]);
        sv1 = f4(&score_w[lane * 8 + 4]);
    }
    CLUSTER_SYNC();

    // ---- decode loop (t == TT is the output-only epilogue) ----
    for (int t = 0; t <= TT; t++) {
        const int cur = t & 1, nxt = cur ^ 1;

        // ================= PHASE A =================
        if (wid >= 24) {
            // output heads for step t-1 (5 warps cover 38 outputs)
            if (t > 0 && wid < 29) {
                int ow = r + 8 * (wid - 24);
                if (ow < OUTW) {
                    float4 h0 = f4(&sm->hid[cur][lane * 8]);
                    float4 h1 = f4(&sm->hid[cur][lane * 8 + 4]);
                    const float* wr = g_Wcomb + ow * HID + lane * 8;
                    float4 w0 = f4(wr), w1 = f4(wr + 4);
                    float a = w0.x * h0.x + w0.y * h0.y + w0.z * h0.z + w0.w * h0.w
                            + w1.x * h1.x + w1.y * h1.y + w1.z * h1.z + w1.w * h1.w;
                    #pragma unroll
                    for (int o = 16; o > 0; o >>= 1) a += __shfl_xor_sync(0xffffffffu, a, o);
                    if (lane == 0) {
                        a += g_bcomb[ow];
                        if (ow >= NEMB) a = sigmoidf_(a);
                        out[((size_t)b * TT + (t - 1)) * OUTW + ow] = a;
                    }
                }
            }
        } else if (t < TT) {
            // assemble full prev_proj: sum of 8 column-partials + bias
            if (tid < HID) {
                uint32_t base = smem_u32(&sm->pp_part[tid]);
                float acc = sm->h2hb[tid];
                #pragma unroll
                for (int p = 0; p < RCL; p++) acc += ld_dsm(mapa_u32(base, p));
                sm->pp[tid] = acc;
            }
            BAR1_768();
            // attention: rows 2*wid, 2*wid+1 (+48+wid for wid<2)
            {
                float4 pv0 = f4(&sm->pp[lane * 8]);
                float4 pv1 = f4(&sm->pp[lane * 8 + 4]);
                int rows[3]; int nr = 2;
                rows[0] = 2 * wid; rows[1] = 2 * wid + 1;
                if (wid < 2) { rows[2] = 48 + wid; nr = 3; }
                for (int q = 0; q < nr; q++) {
                    int n = rows[q];
                    const float* hp = &sm->hproj[n * HID + lane * 8];
                    float4 h0 = f4(hp), h1 = f4(hp + 4);
                    float a = tanh_fast(h0.x + pv0.x) * sv0.x
                            + tanh_fast(h0.y + pv0.y) * sv0.y
                            + tanh_fast(h0.z + pv0.z) * sv0.z
                            + tanh_fast(h0.w + pv0.w) * sv0.w
                            + tanh_fast(h1.x + pv1.x) * sv1.x
                            + tanh_fast(h1.y + pv1.y) * sv1.y
                            + tanh_fast(h1.z + pv1.z) * sv1.z
                            + tanh_fast(h1.w + pv1.w) * sv1.w;
                    #pragma unroll
                    for (int o = 16; o > 0; o >>= 1) a += __shfl_xor_sync(0xffffffffu, a, o);
                    if (lane == 0) sm->wexp[n] = __expf(a);
                }
            }
            BAR1_768();
            if (wid < 4) {           // partial context, 128 threads x float4
                float4 a = make_float4(0.f, 0.f, 0.f, 0.f);
                #pragma unroll 5
                for (int n = 0; n < NLOC; n++) {
                    float w = sm->wexp[n];
                    float4 fv = f4(&sm->feat[n * FSTR + tid * 4]);
                    a.x += w * fv.x; a.y += w * fv.y; a.z += w * fv.z; a.w += w * fv.w;
                }
                *(float4*)&sm->part_ctx[tid * 4] = a;
            }
            if (wid == 16) {         // local expsum -> part_ctx[512]
                float v = (lane < 25) ? sm->wexp[lane] + sm->wexp[lane + 25] : 0.f;
                #pragma unroll
                for (int o = 16; o > 0; o >>= 1) v += __shfl_xor_sync(0xffffffffu, v, o);
                if (lane == 0) sm->part_ctx[512] = v;
            }
        }
        if (t == TT) break;

        CLUSTER_SYNC();   // S1: part_ctx (incl es) ready everywhere

        // ================= PHASE B =================
        // ctx all-reduce by direct 8-peer pull (threads 0..512, rank-uniform)
        if (tid < 513) {
            uint32_t base = smem_u32(&sm->part_ctx[tid]);
            float acc = 0.f;
            #pragma unroll
            for (int p = 0; p < RCL; p++) acc += ld_dsm(mapa_u32(base, p));
            sm->ctxS[tid] = acc;
        }
        // concurrently: gh = whh @ hid + bhh (warps 24..31, 12 rows each)
        if (wid >= 24) {
            float4 h0 = f4(&sm->hid[cur][lane * 8]);
            float4 h1 = f4(&sm->hid[cur][lane * 8 + 4]);
            #pragma unroll 4
            for (int i = 0; i < 12; i++) {
                int m2 = (wid - 24) * 12 + i;     // 0..95
                int g  = m2 >> 5, u = m2 & 31;
                const float* wr = whh + (size_t)(g * HID + r * 32 + u) * HID + lane * 8;
                float4 w0 = f4(wr), w1 = f4(wr + 4);
                float a = w0.x * h0.x + w0.y * h0.y + w0.z * h0.z + w0.w * h0.w
                        + w1.x * h1.x + w1.y * h1.y + w1.z * h1.z + w1.w * h1.w;
                #pragma unroll
                for (int o = 16; o > 0; o >>= 1) a += __shfl_xor_sync(0xffffffffu, a, o);
                if (lane == 0) sm->gh[m2] = a + bhh[g * HID + r * 32 + u];
            }
        }
        __syncthreads();

        // GRU input GEMV + cell update; warp wid owns unit j = r*32+wid
        {
            const int ch = structure[b * TT + t];
            const int j  = r * 32 + wid;
            float4 c0 = f4(&sm->ctxS[0 * 128 + lane * 4]);
            float4 c1 = f4(&sm->ctxS[1 * 128 + lane * 4]);
            float4 c2 = f4(&sm->ctxS[2 * 128 + lane * 4]);
            float4 c3 = f4(&sm->ctxS[3 * 128 + lane * 4]);
            float ag[3];
            #pragma unroll
            for (int g = 0; g < 3; g++) {
                const float* wr = g_wihP + (size_t)(g * HID + j) * XP + lane * 4;
                float4 w0 = f4(wr), w1 = f4(wr + 128), w2 = f4(wr + 256), w3 = f4(wr + 384);
                float a = w0.x * c0.x + w0.y * c0.y + w0.z * c0.z + w0.w * c0.w;
                a += w1.x * c1.x + w1.y * c1.y + w1.z * c1.z + w1.w * c1.w;
                a += w2.x * c2.x + w2.y * c2.y + w2.z * c2.z + w2.w * c2.w;
                a += w3.x * c3.x + w3.y * c3.y + w3.z * c3.z + w3.w * c3.w;
                ag[g] = a;
            }
            #pragma unroll
            for (int o = 16; o > 0; o >>= 1) {
                ag[0] += __shfl_xor_sync(0xffffffffu, ag[0], o);
                ag[1] += __shfl_xor_sync(0xffffffffu, ag[1], o);
                ag[2] += __shfl_xor_sync(0xffffffffu, ag[2], o);
            }
            float hnew = 0.f;
            if (lane == 0) {
                float inv = __fdividef(1.f, sm->ctxS[512]);
                float ir  = ag[0] * inv + g_wihP[(size_t)(0 * HID + j) * XP + 512 + ch];
                float iz  = ag[1] * inv + g_wihP[(size_t)(1 * HID + j) * XP + 512 + ch];
                float in_ = ag[2] * inv + g_wihP[(size_t)(2 * HID + j) * XP + 512 + ch];
                float hr = sm->gh[wid], hz = sm->gh[32 + wid], hn = sm->gh[64 + wid];
                float rg = sigmoidf_(ir + hr);
                float zg = sigmoidf_(iz + hz);
                float ng = tanh_acc(in_ + rg * hn);
                hnew = (1.f - zg) * ng + zg * sm->hid[cur][j];
            }
            hnew = __shfl_sync(0xffffffffu, hnew, 0);
            if (lane < RCL)
                st_dsm(mapa_u32(smem_u32(&sm->hid[nxt][j]), lane), hnew);
            if (lane == 0) sm->hloc[wid] = hnew;
        }
        __syncthreads();
        // column-partial of next prev_proj from SMEM-cached h2hT slice (8 warps)
        if (tid < HID) {
            float a = 0.f;
            #pragma unroll 8
            for (int k = 0; k < 32; k++)
                a += sm->hloc[k] * sm->h2hs[k * HID + tid];
            sm->pp_part[tid] = a;
        }
        CLUSTER_SYNC();   // S2: pp_part + hid[nxt] ready for next step
    }
}

// ---------------- launch ----------------
extern "C" void kernel_launch(void* const* d_in, const int* in_sizes, int n_in,
                              void* d_out, int out_size) {
    const float* fea       = (const float*)d_in[0];
    const int*   structure = (const int*)  d_in[1];
    const float* i2h_w     = (const float*)d_in[2];
    const float* h2h_w     = (const float*)d_in[3];
    const float* h2h_b     = (const float*)d_in[4];
    const float* score_w   = (const float*)d_in[5];
    const float* gru_wih   = (const float*)d_in[6];
    const float* gru_bih   = (const float*)d_in[7];
    const float* gru_whh   = (const float*)d_in[8];
    const float* gru_bhh   = (const float*)d_in[9];
    const float* sg1_w     = (const float*)d_in[10];
    const float* sg1_b     = (const float*)d_in[11];
    const float* sg2_w     = (const float*)d_in[12];
    const float* sg2_b     = (const float*)d_in[13];
    const float* lg1_w     = (const float*)d_in[14];
    const float* lg1_b     = (const float*)d_in[15];
    const float* lg2_w     = (const float*)d_in[16];
    const float* lg2_b     = (const float*)d_in[17];
    float* out = (float*)d_out;

    prep_kernel<<<OUTW + CC + HID + 3 * HID, HID>>>(
        i2h_w, h2h_w, gru_wih, gru_bih,
        sg1_w, sg1_b, sg2_w, sg2_b, lg1_w, lg1_b, lg2_w, lg2_b);

    cudaFuncSetAttribute(sla_kernel, cudaFuncAttributeMaxDynamicSharedMemorySize,
                         (int)sizeof(Smem));
    sla_kernel<<<BB * RCL, NTHR, sizeof(Smem)>>>(
        fea, structure, h2h_b, score_w, gru_whh, gru_bhh, out);
}